// round 8
// baseline (speedup 1.0000x reference)
#include <cuda_runtime.h>
#include <math_constants.h>

#define NA    2     // anchors per block
#define GRID  128   // 128 * 2 = 256 anchors, single wave on 148+ SMs
#define NT    256   // 8 warps; warp w owns rows [32w, 32w+32)

__device__ float        g_sum;
__device__ float        g_cnt;
__device__ unsigned int g_ticket;

__global__ void __launch_bounds__(NT, 1)
triplet_fused(const float* __restrict__ emb,
              const int* __restrict__ labraw,
              float* __restrict__ out) {
    __shared__ float dkS[NA][260];     // d[ia, j] rows (260%32==4 -> conflict-free)
    __shared__ int   labsh[256];
    __shared__ int   s_plist[NA * 256];
    __shared__ float s_wmax[NA][8];
    __shared__ float s_maxneg[NA];
    __shared__ int   s_is64;
    __shared__ int   s_npos;
    __shared__ float s_bsum;

    const int t    = threadIdx.x;
    const int lane = t & 31;
    const int w    = t >> 5;
    const int ib   = blockIdx.x * NA;

    if (t == 0) { s_is64 = 1; s_npos = 0; s_bsum = 0.f; }
    __syncthreads();

    // label dtype detect: int64 labels in [0,16) have zero high words.
    // Touches only the first 1KB (in-bounds for both int32[256] and int64[256]).
    if (t < 128 && labraw[2 * t + 1] != 0) s_is64 = 0;   // benign race: all store 0

    // ---- anchor rows into registers, lane-sliced (coalesced; redundant per warp) ----
    const float4* src = (const float4*)emb;              // 32 float4 per row
    const float4  a0  = src[(ib + 0) * 32 + lane];
    const float4  a1  = src[(ib + 1) * 32 + lane];

    // anchor norms (each warp computes redundantly; 10 shfl once)
    float an0 = a0.x * a0.x + a0.y * a0.y + a0.z * a0.z + a0.w * a0.w;
    float an1 = a1.x * a1.x + a1.y * a1.y + a1.z * a1.z + a1.w * a1.w;
    #pragma unroll
    for (int off = 16; off; off >>= 1) {
        an0 += __shfl_xor_sync(~0u, an0, off);
        an1 += __shfl_xor_sync(~0u, an1, off);
    }

    __syncthreads();
    labsh[t] = s_is64 ? labraw[2 * t] : labraw[t];

    // ---- phase 1: warp-cooperative distance rows straight from global ----
    const int jbase = w * 32;
    #pragma unroll 8
    for (int jj = 0; jj < 32; jj++) {
        const int    j = jbase + jj;
        const float4 v = src[j * 32 + lane];             // coalesced LDG.128
        float pn = v.x * v.x  + v.y * v.y  + v.z * v.z  + v.w * v.w;
        float p0 = v.x * a0.x + v.y * a0.y + v.z * a0.z + v.w * a0.w;
        float p1 = v.x * a1.x + v.y * a1.y + v.z * a1.z + v.w * a1.w;
        #pragma unroll
        for (int off = 16; off; off >>= 1) {
            pn += __shfl_xor_sync(~0u, pn, off);
            p0 += __shfl_xor_sync(~0u, p0, off);
            p1 += __shfl_xor_sync(~0u, p1, off);
        }
        if (lane == 0) {
            dkS[0][j] = sqrtf(fmaxf(an0 + pn - 2.f * p0, 1e-4f));
            dkS[1][j] = sqrtf(fmaxf(an1 + pn - 2.f * p1, 1e-4f));
        }
    }
    __syncthreads();

    // ---- positives list + per-anchor maxNeg ----
    const int labt = labsh[t];
    #pragma unroll
    for (int a = 0; a < NA; a++) {
        const int   ia = ib + a;
        const float dv = dkS[a][t];
        const bool neg = (labt != labsh[ia]) || (t == ia);  // (1-pos) incl. diagonal
        if (!neg) { int p = atomicAdd(&s_npos, 1); s_plist[p] = (a << 8) | t; }
        float m = neg ? dv : -CUDART_INF_F;
        #pragma unroll
        for (int off = 16; off; off >>= 1) m = fmaxf(m, __shfl_xor_sync(~0u, m, off));
        if (lane == 0) s_wmax[a][w] = m;
    }
    __syncthreads();
    if (t < NA) {
        float mm = s_wmax[t][0];
        #pragma unroll
        for (int q = 1; q < 8; q++) mm = fmaxf(mm, s_wmax[t][q]);
        s_maxneg[t] = mm;
    }
    __syncthreads();

    // ---- phase 2: warp-cooperative semi-hard scan over positives ----
    const int np = s_npos;
    float wsum = 0.f;
    for (int p = w; p < np; p += 8) {
        const int   e   = s_plist[p];
        const int   a   = e >> 8;
        const int   k   = e & 255;
        const int   ia  = ib + a;
        const int   la  = labsh[ia];
        const float dkk = dkS[a][k];
        float mg = CUDART_INF_F;       // min over negatives with d > dkk
        #pragma unroll
        for (int q = 0; q < 8; q++) {
            const int   jj = lane + 32 * q;          // one bank per lane
            const float dj = dkS[a][jj];
            const bool  ng = (labsh[jj] != la) || (jj == ia);
            mg = fminf(mg, (ng && dj > dkk) ? dj : CUDART_INF_F);
        }
        #pragma unroll
        for (int off = 16; off; off >>= 1) mg = fminf(mg, __shfl_xor_sync(~0u, mg, off));
        float v = (mg < CUDART_INF_F) ? (dkk - mg)           // semi-hard exists
                                      : (dkk - s_maxneg[a]); // fallback: easiest neg
        wsum += fmaxf(v + 1.0f, 0.f);                        // relu(semi_hard + MARGIN)
    }
    if (lane == 0 && wsum != 0.f) atomicAdd(&s_bsum, wsum);
    __syncthreads();

    // ---- last-block-done epilogue (single kernel) ----
    if (t == 0) {
        atomicAdd(&g_sum, s_bsum);
        atomicAdd(&g_cnt, (float)np);
        __threadfence();
        unsigned tk = atomicAdd(&g_ticket, 1u);
        if (tk == GRID - 1) {
            __threadfence();
            float s = atomicAdd(&g_sum, 0.f);
            float c = atomicAdd(&g_cnt, 0.f);
            out[0] = s / c;
            g_sum = 0.f;          // reset for next graph replay
            g_cnt = 0.f;
            __threadfence();
            g_ticket = 0u;
        }
    }
}

extern "C" void kernel_launch(void* const* d_in, const int* in_sizes, int n_in,
                              void* d_out, int out_size) {
    const float* emb    = (const float*)d_in[0];   // [256, 128] float32
    const int*   labraw = (const int*)d_in[1];     // [256] labels (int64/int32 detected)
    float* out = (float*)d_out;

    triplet_fused<<<GRID, NT>>>(emb, labraw, out);
}

// round 9
// speedup vs baseline: 1.4341x; 1.4341x over previous
#include <cuda_runtime.h>
#include <cuda_pipeline.h>
#include <math_constants.h>

#define NA    4     // anchors per block
#define GRID  64    // 64 * 4 = 256 anchors, single wave
#define NT    256
#define ROWW  132   // padded row stride (floats): conflict-free LDS.128

__device__ float        g_sum;
__device__ float        g_cnt;
__device__ unsigned int g_ticket;

extern __shared__ float semb[];   // 256 * ROWW floats = 135168 B (dynamic)

typedef unsigned long long ull;

// packed fp32x2 FMA (sm_10x FFMA2): d = a*b + c, lane-wise exact fp32
static __device__ __forceinline__ ull fma2(ull a, ull b, ull c) {
    ull d;
    asm("fma.rn.f32x2 %0, %1, %2, %3;" : "=l"(d) : "l"(a), "l"(b), "l"(c));
    return d;
}
static __device__ __forceinline__ float lohi(ull a) {
    float lo = __uint_as_float((unsigned)a);
    float hi = __uint_as_float((unsigned)(a >> 32));
    return lo + hi;
}

__global__ void __launch_bounds__(NT, 1)
triplet_fused(const float* __restrict__ emb,
              const int* __restrict__ labraw,
              float* __restrict__ out) {
    __shared__ float sanchA[NA * 128];   // anchor rows for threads 0-127
    __shared__ float sanchB[NA * 128];   // anchor rows for threads 128-255
    __shared__ float dkS[NA][260];       // d[ia, j]   (260%32==4 -> conflict-free)
    __shared__ float dnegS[NA][260];     // d if j negative else -inf
    __shared__ float normS[256];
    __shared__ int   s_plist[NA * 256];
    __shared__ int   s_is64;
    __shared__ int   s_npos;
    __shared__ float s_bsum;

    const int t    = threadIdx.x;
    const int half = t >> 7;             // 0: rows 0-127, 1: rows 128-255
    const int tt   = t & 127;
    const int ib   = blockIdx.x * NA;

    if (t == 0) { s_is64 = 1; s_npos = 0; s_bsum = 0.f; }
    __syncthreads();

    // ---- group-private async staging (each half stages its own rows + anchors) ----
    const float4* src   = (const float4*)emb;    // 32 float4 per row
    float*        sanch = half ? sanchB : sanchA;
    {   // anchor rows: 4*32 = 128 float4, one per thread of the group
        int r = tt >> 5, c4 = tt & 31;
        __pipeline_memcpy_async(sanch + r * 128 + c4 * 4, src + (ib + r) * 32 + c4, 16);
    }
    #pragma unroll
    for (int k = 0; k < 32; k++) {       // 128 rows = 4096 float4 per group
        int idx4 = half * 4096 + k * 128 + tt;   // coalesced
        int r = idx4 >> 5, c4 = idx4 & 31;
        __pipeline_memcpy_async(semb + r * ROWW + c4 * 4, src + idx4, 16);
    }
    __pipeline_commit();

    // label dtype detect while copies fly: int64 labels in [0,16) have zero
    // high words; touches only first 1KB (in-bounds for int32[256] too).
    if (t < 128 && labraw[2 * t + 1] != 0) s_is64 = 0;   // benign race: all store 0

    __pipeline_wait_prior(0);
    // per-half barrier: our half's rows+anchors were issued only by our 128 threads
    asm volatile("bar.sync %0, 128;" :: "r"(1 + half) : "memory");

    // ---- phase 1: dot of row t vs 4 anchors, packed f32x2 FMA ----
    const ulonglong2* rT = (const ulonglong2*)(semb + t * ROWW);   // 16 x (2 f32x2)
    const ulonglong2* A0 = (const ulonglong2*)(sanch + 0 * 128);
    const ulonglong2* A1 = (const ulonglong2*)(sanch + 1 * 128);
    const ulonglong2* A2 = (const ulonglong2*)(sanch + 2 * 128);
    const ulonglong2* A3 = (const ulonglong2*)(sanch + 3 * 128);

    ull n0 = 0, n1 = 0;
    ull d00 = 0, d01 = 0, d10 = 0, d11 = 0, d20 = 0, d21 = 0, d30 = 0, d31 = 0;
    #pragma unroll
    for (int c = 0; c < 16; c++) {
        ulonglong2 v  = rT[c];
        ulonglong2 a0 = A0[c];               // broadcast LDS
        ulonglong2 a1 = A1[c];
        ulonglong2 a2 = A2[c];
        ulonglong2 a3 = A3[c];
        n0  = fma2(v.x, v.x,  n0);  n1  = fma2(v.y, v.y,  n1);
        d00 = fma2(v.x, a0.x, d00); d01 = fma2(v.y, a0.y, d01);
        d10 = fma2(v.x, a1.x, d10); d11 = fma2(v.y, a1.y, d11);
        d20 = fma2(v.x, a2.x, d20); d21 = fma2(v.y, a2.y, d21);
        d30 = fma2(v.x, a3.x, d30); d31 = fma2(v.y, a3.y, d31);
    }
    const float nj = lohi(n0) + lohi(n1);
    float dotv[NA] = { lohi(d00) + lohi(d01), lohi(d10) + lohi(d11),
                       lohi(d20) + lohi(d21), lohi(d30) + lohi(d31) };
    normS[t] = nj;
    __syncthreads();     // norms from both halves + s_is64 settled

    // ---- dk, neg mask, positives list (labels straight from global, L2-hot) ----
    const int is64 = s_is64;
    const int labT = is64 ? labraw[2 * t] : labraw[t];
    #pragma unroll
    for (int a = 0; a < NA; a++) {
        const int ia   = ib + a;
        const int labA = is64 ? labraw[2 * ia] : labraw[ia];
        const float dv = sqrtf(fmaxf(normS[ia] + nj - 2.f * dotv[a], 1e-4f));
        dkS[a][t] = dv;
        const bool neg = (labT != labA) || (t == ia);   // (1-pos) incl. diagonal
        dnegS[a][t] = neg ? dv : -CUDART_INF_F;
        if (!neg) { int p = atomicAdd(&s_npos, 1); s_plist[p] = (a << 8) | t; }
    }
    #pragma unroll
    for (int a = 0; a < NA; a++) if (t < 4) dnegS[a][256 + t] = -CUDART_INF_F; // pad
    __syncthreads();

    // ---- phase 2: thread-per-positive scan; max folded into the same pass ----
    const int np = s_npos;
    float contrib = 0.f;
    for (int p = t; p < np; p += NT) {
        const int   e   = s_plist[p];
        const int   a   = e >> 8;
        const int   k   = e & 255;
        const float dkk = dkS[a][k];
        const float4* dn = (const float4*)dnegS[a];    // 16B-aligned (a*1040B)
        float m0 = CUDART_INF_F, m1 = CUDART_INF_F, m2 = CUDART_INF_F, m3 = CUDART_INF_F;
        float x0 = -CUDART_INF_F, x1 = -CUDART_INF_F, x2 = -CUDART_INF_F, x3 = -CUDART_INF_F;
        #pragma unroll 8
        for (int j = 0; j < 64; j++) {                 // 64 x float4 = 256
            float4 d4 = dn[j];
            m0 = fminf(m0, d4.x > dkk ? d4.x : CUDART_INF_F); x0 = fmaxf(x0, d4.x);
            m1 = fminf(m1, d4.y > dkk ? d4.y : CUDART_INF_F); x1 = fmaxf(x1, d4.y);
            m2 = fminf(m2, d4.z > dkk ? d4.z : CUDART_INF_F); x2 = fmaxf(x2, d4.z);
            m3 = fminf(m3, d4.w > dkk ? d4.w : CUDART_INF_F); x3 = fmaxf(x3, d4.w);
        }
        const float mg = fminf(fminf(m0, m1), fminf(m2, m3));  // min neg with d > dkk
        const float mx = fmaxf(fmaxf(x0, x1), fmaxf(x2, x3));  // max over all negs
        const float v  = (mg < CUDART_INF_F) ? (dkk - mg)      // semi-hard exists
                                             : (dkk - mx);     // fallback: easiest neg
        contrib += fmaxf(v + 1.0f, 0.f);                       // relu(semi_hard+MARGIN)
    }
    if (contrib != 0.f) atomicAdd(&s_bsum, contrib);
    __syncthreads();

    // ---- last-block-done epilogue (single kernel) ----
    if (t == 0) {
        atomicAdd(&g_sum, s_bsum);
        atomicAdd(&g_cnt, (float)np);
        __threadfence();
        unsigned tk = atomicAdd(&g_ticket, 1u);
        if (tk == GRID - 1) {
            __threadfence();
            float s = atomicAdd(&g_sum, 0.f);
            float c = atomicAdd(&g_cnt, 0.f);
            out[0] = s / c;
            g_sum = 0.f;          // reset for next graph replay
            g_cnt = 0.f;
            __threadfence();
            g_ticket = 0u;
        }
    }
}

extern "C" void kernel_launch(void* const* d_in, const int* in_sizes, int n_in,
                              void* d_out, int out_size) {
    const float* emb    = (const float*)d_in[0];   // [256, 128] float32
    const int*   labraw = (const int*)d_in[1];     // [256] labels (int64/int32 detected)
    float* out = (float*)d_out;

    const int smem = 256 * ROWW * sizeof(float);   // 135168 B
    cudaFuncSetAttribute(triplet_fused, cudaFuncAttributeMaxDynamicSharedMemorySize, smem);
    triplet_fused<<<GRID, NT, smem>>>(emb, labraw, out);
}

// round 10
// speedup vs baseline: 1.6642x; 1.1604x over previous
#include <cuda_runtime.h>
#include <cuda_pipeline.h>
#include <math_constants.h>

#define NA    2     // anchors per block
#define GRID  128   // 128 * 2 = 256 anchors, single wave on 148 SMs
#define NT    256   // 8 warps; warp w owns rows [32w, 32w+32)
#define ROWW  132   // padded row stride (floats): conflict-free LDS.128

__device__ float        g_sum;
__device__ float        g_cnt;
__device__ unsigned int g_ticket;

extern __shared__ float semb[];   // 256 * ROWW floats = 135168 B (dynamic)

__global__ void __launch_bounds__(NT, 1)
triplet_fused(const float* __restrict__ emb,
              const int* __restrict__ labraw,
              float* __restrict__ out) {
    __shared__ float sanch[8][NA * 128 + 4];   // per-warp anchor copies (pad vs conflicts)
    __shared__ float dnegS[NA][260];           // d[ia,j] if j negative else -inf (+pad)
    __shared__ float normS[256];
    __shared__ int   s_is64;
    __shared__ int   s_npos;
    __shared__ float s_bsum;

    const int t    = threadIdx.x;
    const int lane = t & 31;
    const int w    = t >> 5;
    const int ib   = blockIdx.x * NA;

    if (t == 0) { s_is64 = 1; s_npos = 0; s_bsum = 0.f; }

    // label dtype detect: int64 labels in [0,16) have zero high words.
    // Touches only the first 1KB (in-bounds for both int32[256] and int64[256]).
    const int hi = (t < 128) ? labraw[2 * t + 1] : 0;

    // prefetch both dtype interpretations (selected after the norm barrier)
    const int lt64  = labraw[2 * t],        lt32  = labraw[t];
    const int la64a = labraw[2 * ib],       la32a = labraw[ib];
    const int la64b = labraw[2 * (ib + 1)], la32b = labraw[ib + 1];

    // ---- warp-private async staging: warp w stages rows [32w,32w+32) + anchors ----
    const float4* src = (const float4*)emb;            // 32 float4 per row
    float*        anc = sanch[w];
    #pragma unroll
    for (int a = 0; a < NA; a++)                       // 2 anchor rows per warp copy
        __pipeline_memcpy_async(anc + a * 128 + lane * 4, src + (ib + a) * 32 + lane, 16);
    #pragma unroll
    for (int k = 0; k < 32; k++) {                     // own rows, coalesced per k
        const int r = 32 * w + k;
        __pipeline_memcpy_async(semb + r * ROWW + lane * 4, src + r * 32 + lane, 16);
    }
    __pipeline_commit();

    if (hi != 0) s_is64 = 0;                           // benign race: all writers store 0

    __pipeline_wait_prior(0);
    __syncwarp();          // this warp reads only rows/anchors staged by this warp

    // ---- phase 1: dot of row t vs NA anchors (EXACT R7 ordering -> rel_err 0) ----
    const float* rowT  = semb + t * ROWW;
    const float* rowA0 = anc;
    const float* rowA1 = anc + 128;
    float d0 = 0.f, d1 = 0.f, nj = 0.f;
    #pragma unroll
    for (int c = 0; c < 128; c += 4) {
        float4 a  = *(const float4*)(rowT + c);
        float4 b0 = *(const float4*)(rowA0 + c);       // broadcast LDS
        float4 b1 = *(const float4*)(rowA1 + c);
        nj += a.x * a.x  + a.y * a.y  + a.z * a.z  + a.w * a.w;
        d0 += a.x * b0.x + a.y * b0.y + a.z * b0.z + a.w * b0.w;
        d1 += a.x * b1.x + a.y * b1.y + a.z * b1.z + a.w * b1.w;
    }
    normS[t] = nj;
    __syncthreads();                                   // norms + s_is64 settled

    // ---- dk, neg mask, positive flags ----
    const int  is64 = s_is64;
    const int  labT = is64 ? lt64 : lt32;
    const int  labA[NA] = { is64 ? la64a : la32a, is64 ? la64b : la32b };
    const float dotv[NA] = { d0, d1 };
    float dkk[NA];
    bool  pos[NA];
    #pragma unroll
    for (int a = 0; a < NA; a++) {
        const int ia = ib + a;
        dkk[a] = sqrtf(fmaxf(normS[ia] + nj - 2.f * dotv[a], 1e-4f));
        const bool neg = (labT != labA[a]) || (t == ia);   // (1-pos) incl. diagonal
        pos[a] = !neg;
        dnegS[a][t] = neg ? dkk[a] : -CUDART_INF_F;
        if (t < 4) dnegS[a][256 + t] = -CUDART_INF_F;      // pad (not scanned)
    }
    // npos via ballot (8 atomics total)
    {
        unsigned b0 = __ballot_sync(~0u, pos[0]);
        unsigned b1 = __ballot_sync(~0u, pos[1]);
        if (lane == 0) atomicAdd(&s_npos, __popc(b0) + __popc(b1));
    }
    __syncthreads();

    // ---- phase 2: thread-per-positive scan, min & max folded in one pass ----
    float contrib = 0.f;
    #pragma unroll
    for (int a = 0; a < NA; a++) {
        if (!pos[a]) continue;
        const float dv = dkk[a];
        const float4* dn = (const float4*)&dnegS[a][0];    // 16B aligned (1040B rows)
        float m0 = CUDART_INF_F,  m1 = CUDART_INF_F,  m2 = CUDART_INF_F,  m3 = CUDART_INF_F;
        float x0 = -CUDART_INF_F, x1 = -CUDART_INF_F, x2 = -CUDART_INF_F, x3 = -CUDART_INF_F;
        #pragma unroll 8
        for (int j = 0; j < 64; j++) {                     // 64 x float4 = 256
            float4 q = dn[j];
            m0 = fminf(m0, q.x > dv ? q.x : CUDART_INF_F); x0 = fmaxf(x0, q.x);
            m1 = fminf(m1, q.y > dv ? q.y : CUDART_INF_F); x1 = fmaxf(x1, q.y);
            m2 = fminf(m2, q.z > dv ? q.z : CUDART_INF_F); x2 = fmaxf(x2, q.z);
            m3 = fminf(m3, q.w > dv ? q.w : CUDART_INF_F); x3 = fmaxf(x3, q.w);
        }
        const float mg = fminf(fminf(m0, m1), fminf(m2, m3));  // min neg with d > dv
        const float mx = fmaxf(fmaxf(x0, x1), fmaxf(x2, x3));  // max over all negs
        const float v  = (mg < CUDART_INF_F) ? (dv - mg)       // semi-hard exists
                                             : (dv - mx);      // fallback: easiest neg
        contrib += fmaxf(v + 1.0f, 0.f);                       // relu(semi_hard+MARGIN)
    }
    // warp-reduce then one smem atomic per warp
    #pragma unroll
    for (int off = 16; off; off >>= 1) contrib += __shfl_xor_sync(~0u, contrib, off);
    if (lane == 0 && contrib != 0.f) atomicAdd(&s_bsum, contrib);
    __syncthreads();

    // ---- last-block-done epilogue (single kernel) ----
    if (t == 0) {
        atomicAdd(&g_sum, s_bsum);
        atomicAdd(&g_cnt, (float)s_npos);
        __threadfence();
        unsigned tk = atomicAdd(&g_ticket, 1u);
        if (tk == GRID - 1) {
            __threadfence();
            float s = atomicAdd(&g_sum, 0.f);
            float c = atomicAdd(&g_cnt, 0.f);
            out[0] = s / c;
            g_sum = 0.f;          // reset for next graph replay
            g_cnt = 0.f;
            __threadfence();
            g_ticket = 0u;
        }
    }
}

extern "C" void kernel_launch(void* const* d_in, const int* in_sizes, int n_in,
                              void* d_out, int out_size) {
    const float* emb    = (const float*)d_in[0];   // [256, 128] float32
    const int*   labraw = (const int*)d_in[1];     // [256] labels (int64/int32 detected)
    float* out = (float*)d_out;

    const int smem = 256 * ROWW * sizeof(float);   // 135168 B
    cudaFuncSetAttribute(triplet_fused, cudaFuncAttributeMaxDynamicSharedMemorySize, smem);
    triplet_fused<<<GRID, NT, smem>>>(emb, labraw, out);
}